// round 3
// baseline (speedup 1.0000x reference)
#include <cuda_runtime.h>

// Fused ModernNet inference, f32x2 (FFMA2) + vectorized-LDS version.
// pad(-1) -> conv5x5s2 (1->12) +posbias relu -> pad(-1) -> grouped conv5x5s2
// (3x: 8->4) +posbias relu -> fc 192x30 relu -> fc 30x10.
// 8 samples/block (warp-per-sample), all intermediates in smem, 2 blocks/SM.

#define SPB 8
#define NT  256

typedef unsigned long long ull;

// ---- f32x2 helpers (SASS FFMA2 path) ----
__device__ __forceinline__ ull pack2(float lo, float hi) {
    ull r; asm("mov.b64 %0, {%1, %2};" : "=l"(r) : "f"(lo), "f"(hi)); return r;
}
__device__ __forceinline__ void fma2(ull& d, ull a, ull b) {
    asm("fma.rn.f32x2 %0, %1, %2, %0;" : "+l"(d) : "l"(a), "l"(b));
}
__device__ __forceinline__ ull add2(ull a, ull b) {
    ull r; asm("add.rn.f32x2 %0, %1, %2;" : "=l"(r) : "l"(a), "l"(b)); return r;
}
__device__ __forceinline__ void unpack2(ull v, float& lo, float& hi) {
    asm("mov.b64 {%0, %1}, %2;" : "=f"(lo), "=f"(hi) : "l"(v));
}

// ---- shared memory float offsets (all multiples of 4 for float4/ull access) ----
#define OFF_W1T  0       // conv1 weights transposed [25][12]        300 -> 304
#define OFF_B1T  304     // conv1 bias transposed   [64][12]         768
#define OFF_W2D  1072    // conv2 weights duplicated [12][402]       4824
#define OFF_B2   5896    // conv2 bias [192]
#define OFF_WO   6088    // outw [300]
#define OFF_BO   6388    // outb [10] pad 12
#define OFF_B3   6400    // H3b [30] pad 32
#define OFF_XIN  6432    // padded input 8 * 400 (20x20)
#define OFF_C1   9632    // padded conv1 out, ch-stride 148: 8 * 1776
#define OFF_C2   23840   // conv2 out 8 * 192
#define OFF_F1   25376   // fc1 out 8 * 32
#define SMEM_FLOATS 25632   // 102528 bytes

#define C1_CH_STRIDE 148
#define C1_PER_SAMPLE 1776   // 12 * 148
#define W2_OC_STRIDE 402     // 400 duplicated weights + 2 pad (bank spread)

__global__ void __launch_bounds__(NT, 2) modernnet_kernel(
    const float* __restrict__ x,
    const float* __restrict__ H1w, const float* __restrict__ H1b,
    const float* __restrict__ H2w, const float* __restrict__ H2b,
    const float* __restrict__ H3w, const float* __restrict__ H3b,
    const float* __restrict__ outw, const float* __restrict__ outb,
    float* __restrict__ out, int B)
{
    extern __shared__ float sm[];
    const int tid  = threadIdx.x;
    const int warp = tid >> 5;
    const int lane = tid & 31;
    const int blockSample = blockIdx.x * SPB;

    float* sW1t = sm + OFF_W1T;
    float* sB1t = sm + OFF_B1T;
    float* sW2d = sm + OFF_W2D;
    float* sB2  = sm + OFF_B2;
    float* sWo  = sm + OFF_WO;
    float* sBo  = sm + OFF_BO;
    float* sB3  = sm + OFF_B3;
    float* sXin = sm + OFF_XIN;
    float* sC1  = sm + OFF_C1;
    float* sC2  = sm + OFF_C2;
    float* sF1  = sm + OFF_F1;

    // ---------- Phase 0: weights (transposed/duplicated) + pad fills ----------
    for (int i = tid; i < 300; i += NT) {              // W1t[r][ch] = H1w[ch][r]
        int ch = i / 25, r = i - ch * 25;
        sW1t[r * 12 + ch] = H1w[i];
    }
    for (int i = tid; i < 768; i += NT) {              // B1t[px][ch] = H1b[ch][px]
        int ch = i >> 6, px = i & 63;
        sB1t[px * 12 + ch] = H1b[i];
    }
    for (int i = tid; i < 2400; i += NT) {             // W2d: each weight twice
        int oc = i / 200, r = i - oc * 200;
        float v = H2w[i];
        sW2d[oc * W2_OC_STRIDE + r * 2]     = v;
        sW2d[oc * W2_OC_STRIDE + r * 2 + 1] = v;
    }
    for (int i = tid; i < 192; i += NT) sB2[i] = H2b[i];
    for (int i = tid; i < 300; i += NT) sWo[i] = outw[i];
    if (tid < 10) sBo[tid] = outb[tid];
    if (tid < 30) sB3[tid] = H3b[tid];
    {
        const float4 m1 = make_float4(-1.f, -1.f, -1.f, -1.f);
        float4* f = (float4*)sXin;
        for (int i = tid; i < (SPB * 400) / 4; i += NT) f[i] = m1;
        float4* g = (float4*)sC1;
        for (int i = tid; i < (SPB * C1_PER_SAMPLE) / 4; i += NT) g[i] = m1;
    }
    // CRITICAL: the -1 pad fill above covers the FULL buffers (interior
    // included); phase 1 overwrites interiors from different threads. Must
    // order fill -> scatter across the whole block.
    __syncthreads();

    // ---------- Phase 1: inputs into padded 20x20 buffers ----------
    if (blockSample + SPB <= B) {
        const float4* gx = (const float4*)(x + (size_t)blockSample * 256);
        for (int i = tid; i < SPB * 64; i += NT) {
            float4 v = gx[i];
            int s = i >> 6, rem = i & 63;
            int ih = rem >> 2, iw = (rem & 3) * 4;
            float* d = sXin + s * 400 + (ih + 2) * 20 + iw + 2;
            ((float2*)d)[0] = make_float2(v.x, v.y);
            ((float2*)d)[1] = make_float2(v.z, v.w);
        }
    } else {
        const int nval = (B - blockSample) * 256;
        const float* gx = x + (size_t)blockSample * 256;
        for (int i = tid; i < nval; i += NT) {
            int s = i >> 8, p = i & 255;
            int ih = p >> 4, iw = p & 15;
            sXin[s * 400 + (ih + 2) * 20 + (iw + 2)] = gx[i];
        }
    }
    __syncthreads();

    // ---------- Phase 2: conv1 via f32x2 over channel pairs ----------
    // lane = (quad q of 2x2 output pixels, channel-group chg of 6 channels)
    {
        const int q   = lane & 15;
        const int chg = lane >> 4;
        const int oh0 = (q >> 2) << 1;
        const int ow0 = (q & 3) << 1;
        const float* pbase = sXin + warp * 400 + (oh0 * 2) * 20 + ow0 * 2;
        const float* wT = sW1t + chg * 6;

        ull D[3][7];   // dup-packed input rows, rolling window of 3
        ull acc[2][2][3];
        #pragma unroll
        for (int a = 0; a < 2; a++)
            #pragma unroll
            for (int b = 0; b < 2; b++)
                #pragma unroll
                for (int c = 0; c < 3; c++) acc[a][b][c] = 0ULL;

        #define LOAD_DUP(s, r) do {                                           \
            const float2* rp = (const float2*)(pbase + (r) * 20);             \
            float2 v0 = rp[0], v1 = rp[1], v2 = rp[2], v3 = rp[3];            \
            D[s][0] = pack2(v0.x, v0.x); D[s][1] = pack2(v0.y, v0.y);         \
            D[s][2] = pack2(v1.x, v1.x); D[s][3] = pack2(v1.y, v1.y);         \
            D[s][4] = pack2(v2.x, v2.x); D[s][5] = pack2(v2.y, v2.y);         \
            D[s][6] = pack2(v3.x, v3.x);                                      \
        } while (0)

        LOAD_DUP(0, 0); LOAD_DUP(1, 1); LOAD_DUP(2, 2);

        #pragma unroll
        for (int ki = 0; ki < 5; ki++) {
            if (ki >= 1) LOAD_DUP((ki + 2) % 3, ki + 2);
            const int s0 = ki % 3, s1 = (ki + 2) % 3;
            #pragma unroll
            for (int kj = 0; kj < 5; kj++) {
                const float* wrow = wT + (ki * 5 + kj) * 12;
                ull w0 = *(const ull*)(wrow);
                ull w1 = *(const ull*)(wrow + 2);
                ull w2 = *(const ull*)(wrow + 4);
                #pragma unroll
                for (int pr = 0; pr < 2; pr++) {
                    const int s = pr ? s1 : s0;
                    #pragma unroll
                    for (int pc = 0; pc < 2; pc++) {
                        ull m = D[s][kj + 2 * pc];
                        fma2(acc[pr][pc][0], m, w0);
                        fma2(acc[pr][pc][1], m, w1);
                        fma2(acc[pr][pc][2], m, w2);
                    }
                }
            }
        }
        #undef LOAD_DUP

        float* c1 = sC1 + warp * C1_PER_SAMPLE;
        #pragma unroll
        for (int pr = 0; pr < 2; pr++)
            #pragma unroll
            for (int pc = 0; pc < 2; pc++) {
                const int px   = (oh0 + pr) * 8 + ow0 + pc;
                const int orow = oh0 + pr + 2, ocol = ow0 + pc + 2;
                const float* bp = sB1t + px * 12 + chg * 6;
                #pragma unroll
                for (int ccp = 0; ccp < 3; ccp++) {
                    ull a = add2(acc[pr][pc][ccp], *(const ull*)(bp + 2 * ccp));
                    float v0, v1; unpack2(a, v0, v1);
                    const int ch = chg * 6 + 2 * ccp;
                    c1[ch * C1_CH_STRIDE + orow * 12 + ocol]       = fmaxf(v0, 0.f);
                    c1[(ch + 1) * C1_CH_STRIDE + orow * 12 + ocol] = fmaxf(v1, 0.f);
                }
            }
    }
    __syncwarp();

    // ---------- Phase 3: grouped conv2 via f32x2 over output-col pairs ----------
    // lane<24: oc = lane>>1, half = lane&1 (output rows {0,1} / {2,3})
    if (lane < 24) {
        const int oc   = lane >> 1;
        const int half = lane & 1;
        const int g    = oc >> 2;
        const float* c1    = sC1 + warp * C1_PER_SAMPLE;
        const float* wbase = sW2d + oc * W2_OC_STRIDE;

        ull acc00 = 0, acc01 = 0, acc10 = 0, acc11 = 0;

        #pragma unroll
        for (int ic = 0; ic < 8; ic++) {
            const int inch = ic + ((g == 1) ? 4 : ((g == 2 && ic >= 4) ? 4 : 0));
            const float* ib  = c1 + inch * C1_CH_STRIDE + half * 48;
            const float* wic = wbase + ic * 50;

            ull P[3][9];   // packed pairs (p[x], p[x+2]), rolling 3-row window
            #define LOAD_P_ROW(s, r) do {                                      \
                float4 f0 = *(const float4*)(ib + (r) * 12);                   \
                float4 f1 = *(const float4*)(ib + (r) * 12 + 4);               \
                float4 f2 = *(const float4*)(ib + (r) * 12 + 8);               \
                P[s][0] = pack2(f0.x, f0.z); P[s][1] = pack2(f0.y, f0.w);      \
                P[s][2] = pack2(f0.z, f1.x); P[s][3] = pack2(f0.w, f1.y);      \
                P[s][4] = pack2(f1.x, f1.z); P[s][5] = pack2(f1.y, f1.w);      \
                P[s][6] = pack2(f1.z, f2.x); P[s][7] = pack2(f1.w, f2.y);      \
                P[s][8] = pack2(f2.x, f2.z);                                   \
            } while (0)

            LOAD_P_ROW(0, 0); LOAD_P_ROW(1, 1); LOAD_P_ROW(2, 2);

            #pragma unroll
            for (int ki = 0; ki < 5; ki++) {
                if (ki >= 1) LOAD_P_ROW((ki + 2) % 3, ki + 2);
                const int s0 = ki % 3, s1 = (ki + 2) % 3;
                #pragma unroll
                for (int kj = 0; kj < 5; kj++) {
                    ull wp = *(const ull*)(wic + (ki * 5 + kj) * 2);
                    fma2(acc00, P[s0][kj],     wp);
                    fma2(acc01, P[s0][kj + 4], wp);
                    fma2(acc10, P[s1][kj],     wp);
                    fma2(acc11, P[s1][kj + 4], wp);
                }
            }
            #undef LOAD_P_ROW
        }

        float* c2 = sC2 + warp * 192;
        const int rowb = oc * 16 + half * 8;
        #define EPI(A, IDX) do {                                               \
            ull t = add2(A, *(const ull*)(sB2 + (IDX)));                       \
            float v0, v1; unpack2(t, v0, v1);                                  \
            c2[(IDX)]     = fmaxf(v0, 0.f);                                    \
            c2[(IDX) + 1] = fmaxf(v1, 0.f);                                    \
        } while (0)
        EPI(acc00, rowb + 0); EPI(acc01, rowb + 2);
        EPI(acc10, rowb + 4); EPI(acc11, rowb + 6);
        #undef EPI
    }
    __syncwarp();

    // ---------- Phase 4: fc1 192->30, relu ----------
    if (lane < 30) {
        const float4* a4 = (const float4*)(sC2 + warp * 192);
        const float* w = H3w + lane;
        float acc = sB3[lane];
        #pragma unroll 8
        for (int kk = 0; kk < 48; kk++) {
            float4 v = a4[kk];
            acc = fmaf(v.x, __ldg(w + (4 * kk)     * 30), acc);
            acc = fmaf(v.y, __ldg(w + (4 * kk + 1) * 30), acc);
            acc = fmaf(v.z, __ldg(w + (4 * kk + 2) * 30), acc);
            acc = fmaf(v.w, __ldg(w + (4 * kk + 3) * 30), acc);
        }
        sF1[warp * 32 + lane] = fmaxf(acc, 0.f);
    }
    __syncwarp();

    // ---------- Phase 5: fc2 30->10, direct global store ----------
    if (lane < 10) {
        const float* f = sF1 + warp * 32;
        float acc = sBo[lane];
        #pragma unroll
        for (int k = 0; k < 30; k++)
            acc = fmaf(f[k], sWo[k * 10 + lane], acc);
        const int s = blockSample + warp;
        if (s < B) out[(size_t)s * 10 + lane] = acc;
    }
}

extern "C" void kernel_launch(void* const* d_in, const int* in_sizes, int n_in,
                              void* d_out, int out_size) {
    const float* x    = (const float*)d_in[0];
    const float* H1w  = (const float*)d_in[1];
    const float* H1b  = (const float*)d_in[2];
    const float* H2w  = (const float*)d_in[3];
    const float* H2b  = (const float*)d_in[4];
    const float* H3w  = (const float*)d_in[5];
    const float* H3b  = (const float*)d_in[6];
    const float* outw = (const float*)d_in[7];
    const float* outb = (const float*)d_in[8];

    const int B = in_sizes[0] / 256;
    const int blocks = (B + SPB - 1) / SPB;
    const size_t smem = SMEM_FLOATS * sizeof(float);

    cudaFuncSetAttribute(modernnet_kernel,
                         cudaFuncAttributeMaxDynamicSharedMemorySize, (int)smem);

    modernnet_kernel<<<blocks, NT, smem>>>(x, H1w, H1b, H2w, H2b,
                                           H3w, H3b, outw, outb,
                                           (float*)d_out, B);
}

// round 4
// speedup vs baseline: 1.4431x; 1.4431x over previous
#include <cuda_runtime.h>

// Fused ModernNet inference, vectorized-LDS scalar-FMA version.
// pad(-1) -> conv5x5s2 (1->12) +posbias relu -> pad(-1) -> grouped conv5x5s2
// (3x: 8->4) +posbias relu -> fc 192x30 relu -> fc 30x10.
// 8 samples/block (warp-per-sample), intermediates in smem, 2 blocks/SM.
// A prep kernel pre-pads weights into __device__ globals for float4 access.

#define SPB 8
#define NT  256

// ---- padded weight globals (filled by prep kernel each launch) ----
__device__ float gW1p[12 * 28];     // conv1 w: [ch][28] (25 + 3 zero pad)
__device__ float gW2p[12 * 228];    // conv2 w: [oc][ic*28 + k] (+4 tail pad)
__device__ float gW3p[192 * 32];    // fc1 w:  [k][32] (30 + 2 zero pad)

__global__ void prep_kernel(const float* __restrict__ H1w,
                            const float* __restrict__ H2w,
                            const float* __restrict__ H3w) {
    const int i = blockIdx.x * 256 + threadIdx.x;
    if (i < 336) {
        int ch = i / 28, r = i % 28;
        gW1p[i] = (r < 25) ? H1w[ch * 25 + r] : 0.f;
    }
    if (i < 2736) {
        int oc = i / 228, rem = i % 228;
        int ic = rem / 28, r = rem % 28;
        gW2p[i] = (ic < 8 && r < 25) ? H2w[oc * 200 + ic * 25 + r] : 0.f;
    }
    if (i < 6144) {
        int k = i / 32, n = i % 32;
        gW3p[i] = (n < 30) ? H3w[k * 30 + n] : 0.f;
    }
}

// ---- shared memory float offsets (all div by 4) ----
#define OFF_W1   0       // 336
#define OFF_B1   336     // 768 ([12][64], original layout)
#define OFF_W2   1104    // 2736
#define OFF_B2   3840    // 192
#define OFF_WO   4032    // 300
#define OFF_BO   4332    // 12
#define OFF_B3   4344    // 32 (30 + zero pad)
#define OFF_XIN  4376    // 8 * 400
#define OFF_C1   7576    // 8 * 1776 (ch-stride 148)
#define OFF_C2   21784   // 8 * 192
#define OFF_F1   23320   // 8 * 32
#define SMEM_FLOATS 23576   // 94304 bytes

#define C1_CH_STRIDE 148
#define C1_PER_SAMPLE 1776
#define W2_OC_STRIDE 228

__global__ void __launch_bounds__(NT, 2) modernnet_kernel(
    const float* __restrict__ x,
    const float* __restrict__ H1b, const float* __restrict__ H2b,
    const float* __restrict__ H3b,
    const float* __restrict__ outw, const float* __restrict__ outb,
    float* __restrict__ out, int B)
{
    extern __shared__ float sm[];
    const int tid  = threadIdx.x;
    const int warp = tid >> 5;
    const int lane = tid & 31;
    const int blockSample = blockIdx.x * SPB;

    float* sW1  = sm + OFF_W1;
    float* sB1  = sm + OFF_B1;
    float* sW2  = sm + OFF_W2;
    float* sB2  = sm + OFF_B2;
    float* sWo  = sm + OFF_WO;
    float* sBo  = sm + OFF_BO;
    float* sB3  = sm + OFF_B3;
    float* sXin = sm + OFF_XIN;
    float* sC1  = sm + OFF_C1;
    float* sC2  = sm + OFF_C2;
    float* sF1  = sm + OFF_F1;

    // ---------- Phase 0: vectorized weight copies + pad fills ----------
    {
        float4* d = (float4*)sW1;                    // 336/4 = 84
        const float4* s = (const float4*)gW1p;
        for (int i = tid; i < 84; i += NT) d[i] = s[i];
    }
    {
        float4* d = (float4*)sB1;                    // 768/4 = 192
        const float4* s = (const float4*)H1b;
        for (int i = tid; i < 192; i += NT) d[i] = s[i];
    }
    {
        float4* d = (float4*)sW2;                    // 2736/4 = 684
        const float4* s = (const float4*)gW2p;
        for (int i = tid; i < 684; i += NT) d[i] = s[i];
    }
    {
        float4* d = (float4*)sB2;                    // 192/4 = 48
        const float4* s = (const float4*)H2b;
        for (int i = tid; i < 48; i += NT) d[i] = s[i];
    }
    {
        float4* d = (float4*)sWo;                    // 300/4 = 75
        const float4* s = (const float4*)outw;
        for (int i = tid; i < 75; i += NT) d[i] = s[i];
    }
    if (tid < 12) sBo[tid] = (tid < 10) ? outb[tid] : 0.f;
    if (tid < 32) sB3[tid] = (tid < 30) ? H3b[tid] : 0.f;
    {
        const float4 m1 = make_float4(-1.f, -1.f, -1.f, -1.f);
        float4* f = (float4*)sXin;
        for (int i = tid; i < (SPB * 400) / 4; i += NT) f[i] = m1;
        float4* g = (float4*)sC1;
        for (int i = tid; i < (SPB * C1_PER_SAMPLE) / 4; i += NT) g[i] = m1;
    }
    // Fill -> scatter ordering across whole block (required!)
    __syncthreads();

    // ---------- Phase 1: inputs into padded 20x20 buffers ----------
    if (blockSample + SPB <= B) {
        const float4* gx = (const float4*)(x + (size_t)blockSample * 256);
        for (int i = tid; i < SPB * 64; i += NT) {
            float4 v = gx[i];
            int s = i >> 6, rem = i & 63;
            int ih = rem >> 2, iw = (rem & 3) * 4;
            float* d = sXin + s * 400 + (ih + 2) * 20 + iw + 2;
            ((float2*)d)[0] = make_float2(v.x, v.y);
            ((float2*)d)[1] = make_float2(v.z, v.w);
        }
    } else {
        const int nval = (B - blockSample) * 256;
        const float* gx = x + (size_t)blockSample * 256;
        for (int i = tid; i < nval; i += NT) {
            int s = i >> 8, p = i & 255;
            int ih = p >> 4, iw = p & 15;
            sXin[s * 400 + (ih + 2) * 20 + (iw + 2)] = gx[i];
        }
    }
    __syncthreads();

    // ---------- Phase 2: conv1 5x5 s2, 1->12 ch, posbias, relu ----------
    // lane: quad q (2x2 output pixels), channel-group chg of 6 channels
    {
        const int q   = lane & 15;
        const int chg = lane >> 4;
        const int oh0 = (q >> 2) << 1;
        const int ow0 = (q & 3) << 1;
        const float* pbase = sXin + warp * 400 + (2 * oh0) * 20 + 2 * ow0;

        // 7 rows x 8 cols of input via 2 float4 per row (use cols 0..6)
        float p[7][8];
        #pragma unroll
        for (int i = 0; i < 7; i++) {
            float4 v0 = *(const float4*)(pbase + i * 20);
            float4 v1 = *(const float4*)(pbase + i * 20 + 4);
            p[i][0] = v0.x; p[i][1] = v0.y; p[i][2] = v0.z; p[i][3] = v0.w;
            p[i][4] = v1.x; p[i][5] = v1.y; p[i][6] = v1.z; p[i][7] = v1.w;
        }

        float* c1 = sC1 + warp * C1_PER_SAMPLE;
        #pragma unroll
        for (int cc = 0; cc < 6; cc++) {
            const int c = chg * 6 + cc;
            // weights: 7 float4 (25 used of 28)
            const float4* w4 = (const float4*)(sW1 + c * 28);
            float w[28];
            #pragma unroll
            for (int i = 0; i < 7; i++) {
                float4 v = w4[i];
                w[4 * i] = v.x; w[4 * i + 1] = v.y;
                w[4 * i + 2] = v.z; w[4 * i + 3] = v.w;
            }
            float a00 = 0.f, a01 = 0.f, a10 = 0.f, a11 = 0.f;
            #pragma unroll
            for (int ki = 0; ki < 5; ki++)
                #pragma unroll
                for (int kj = 0; kj < 5; kj++) {
                    const float wv = w[ki * 5 + kj];
                    a00 = fmaf(p[ki][kj],         wv, a00);
                    a01 = fmaf(p[ki][kj + 2],     wv, a01);
                    a10 = fmaf(p[ki + 2][kj],     wv, a10);
                    a11 = fmaf(p[ki + 2][kj + 2], wv, a11);
                }
            // bias (per-position) via float2, relu, store via float2
            const float* b = sB1 + c * 64;
            float2 b0 = *(const float2*)(b + oh0 * 8 + ow0);
            float2 b1 = *(const float2*)(b + (oh0 + 1) * 8 + ow0);
            float* o = c1 + c * C1_CH_STRIDE;
            *(float2*)(o + (oh0 + 2) * 12 + ow0 + 2) =
                make_float2(fmaxf(a00 + b0.x, 0.f), fmaxf(a01 + b0.y, 0.f));
            *(float2*)(o + (oh0 + 3) * 12 + ow0 + 2) =
                make_float2(fmaxf(a10 + b1.x, 0.f), fmaxf(a11 + b1.y, 0.f));
        }
    }
    __syncwarp();

    // ---------- Phase 3: grouped conv2 5x5 s2, bias, relu ----------
    // lane<24: oc = lane>>1, half = lane&1 (output rows {0,1} / {2,3})
    if (lane < 24) {
        const int oc   = lane >> 1;
        const int half = lane & 1;
        const int g    = oc >> 2;
        const float* c1    = sC1 + warp * C1_PER_SAMPLE;
        const float* wbase = sW2 + oc * W2_OC_STRIDE;

        float acc[2][4];
        #pragma unroll
        for (int r = 0; r < 2; r++)
            #pragma unroll
            for (int c = 0; c < 4; c++) acc[r][c] = 0.f;

        #pragma unroll
        for (int ic = 0; ic < 8; ic++) {
            const int inch = ic + ((g == 1) ? 4 : ((g == 2 && ic >= 4) ? 4 : 0));
            const float* ib = c1 + inch * C1_CH_STRIDE + half * 48;

            // weights for this (oc, ic): 7 float4 (25 used of 28)
            const float4* w4 = (const float4*)(wbase + ic * 28);
            float w[28];
            #pragma unroll
            for (int i = 0; i < 7; i++) {
                float4 v = w4[i];
                w[4 * i] = v.x; w[4 * i + 1] = v.y;
                w[4 * i + 2] = v.z; w[4 * i + 3] = v.w;
            }

            // rolling 3-row window, each row = 12 floats via 3 float4
            float rw[3][12];
            #define LOAD_ROW(s, r) do {                                        \
                float4 f0 = *(const float4*)(ib + (r) * 12);                   \
                float4 f1 = *(const float4*)(ib + (r) * 12 + 4);               \
                float4 f2 = *(const float4*)(ib + (r) * 12 + 8);               \
                rw[s][0] = f0.x; rw[s][1] = f0.y; rw[s][2]  = f0.z; rw[s][3]  = f0.w; \
                rw[s][4] = f1.x; rw[s][5] = f1.y; rw[s][6]  = f1.z; rw[s][7]  = f1.w; \
                rw[s][8] = f2.x; rw[s][9] = f2.y; rw[s][10] = f2.z; rw[s][11] = f2.w; \
            } while (0)

            LOAD_ROW(0, 0); LOAD_ROW(1, 1); LOAD_ROW(2, 2);

            #pragma unroll
            for (int ki = 0; ki < 5; ki++) {
                if (ki >= 1) LOAD_ROW((ki + 2) % 3, ki + 2);
                const int s0 = ki % 3, s1 = (ki + 2) % 3;
                #pragma unroll
                for (int kj = 0; kj < 5; kj++) {
                    const float wv = w[ki * 5 + kj];
                    #pragma unroll
                    for (int c = 0; c < 4; c++) {
                        acc[0][c] = fmaf(rw[s0][2 * c + kj], wv, acc[0][c]);
                        acc[1][c] = fmaf(rw[s1][2 * c + kj], wv, acc[1][c]);
                    }
                }
            }
            #undef LOAD_ROW
        }

        // epilogue: bias + relu, 8 contiguous outputs -> 2 float4 stores
        float* c2 = sC2 + warp * 192;
        const int rowb = oc * 16 + half * 8;
        float4 bA = *(const float4*)(sB2 + rowb);
        float4 bB = *(const float4*)(sB2 + rowb + 4);
        float4 oA, oB;
        oA.x = fmaxf(acc[0][0] + bA.x, 0.f); oA.y = fmaxf(acc[0][1] + bA.y, 0.f);
        oA.z = fmaxf(acc[0][2] + bA.z, 0.f); oA.w = fmaxf(acc[0][3] + bA.w, 0.f);
        oB.x = fmaxf(acc[1][0] + bB.x, 0.f); oB.y = fmaxf(acc[1][1] + bB.y, 0.f);
        oB.z = fmaxf(acc[1][2] + bB.z, 0.f); oB.w = fmaxf(acc[1][3] + bB.w, 0.f);
        *(float4*)(c2 + rowb)     = oA;
        *(float4*)(c2 + rowb + 4) = oB;
    }
    __syncwarp();

    // ---------- Phase 4: fc1 192->30 (padded to 32), relu ----------
    // lane = (neuron-quad L = lane&7, k-slice ks = lane>>3)
    {
        const int L  = lane & 7;
        const int ks = lane >> 3;
        const float4* a4 = (const float4*)(sC2 + warp * 192 + ks * 48);
        float4 acc = make_float4(0.f, 0.f, 0.f, 0.f);
        #pragma unroll
        for (int i = 0; i < 12; i++) {
            float4 av = a4[i];
            const float4* wr = (const float4*)(gW3p + (ks * 48 + 4 * i) * 32 + 4 * L);
            float4 w0 = __ldg(wr);
            float4 w1 = __ldg(wr + 8);
            float4 w2 = __ldg(wr + 16);
            float4 w3 = __ldg(wr + 24);
            acc.x = fmaf(av.x, w0.x, acc.x); acc.y = fmaf(av.x, w0.y, acc.y);
            acc.z = fmaf(av.x, w0.z, acc.z); acc.w = fmaf(av.x, w0.w, acc.w);
            acc.x = fmaf(av.y, w1.x, acc.x); acc.y = fmaf(av.y, w1.y, acc.y);
            acc.z = fmaf(av.y, w1.z, acc.z); acc.w = fmaf(av.y, w1.w, acc.w);
            acc.x = fmaf(av.z, w2.x, acc.x); acc.y = fmaf(av.z, w2.y, acc.y);
            acc.z = fmaf(av.z, w2.z, acc.z); acc.w = fmaf(av.z, w2.w, acc.w);
            acc.x = fmaf(av.w, w3.x, acc.x); acc.y = fmaf(av.w, w3.y, acc.y);
            acc.z = fmaf(av.w, w3.z, acc.z); acc.w = fmaf(av.w, w3.w, acc.w);
        }
        // butterfly reduce across ks (lane bits 3,4)
        #pragma unroll
        for (int off = 16; off >= 8; off >>= 1) {
            acc.x += __shfl_xor_sync(0xffffffffu, acc.x, off);
            acc.y += __shfl_xor_sync(0xffffffffu, acc.y, off);
            acc.z += __shfl_xor_sync(0xffffffffu, acc.z, off);
            acc.w += __shfl_xor_sync(0xffffffffu, acc.w, off);
        }
        if (ks == 0) {
            float4 b = *(const float4*)(sB3 + 4 * L);
            float4 o;
            o.x = fmaxf(acc.x + b.x, 0.f); o.y = fmaxf(acc.y + b.y, 0.f);
            o.z = fmaxf(acc.z + b.z, 0.f); o.w = fmaxf(acc.w + b.w, 0.f);
            *(float4*)(sF1 + warp * 32 + 4 * L) = o;
        }
    }
    __syncwarp();

    // ---------- Phase 5: fc2 30->10, direct global store ----------
    if (lane < 10) {
        const float* f = sF1 + warp * 32;
        float acc = sBo[lane];
        #pragma unroll
        for (int k = 0; k < 30; k++)
            acc = fmaf(f[k], sWo[k * 10 + lane], acc);
        const int s = blockSample + warp;
        if (s < B) out[(size_t)s * 10 + lane] = acc;
    }
}

extern "C" void kernel_launch(void* const* d_in, const int* in_sizes, int n_in,
                              void* d_out, int out_size) {
    const float* x    = (const float*)d_in[0];
    const float* H1w  = (const float*)d_in[1];
    const float* H1b  = (const float*)d_in[2];
    const float* H2w  = (const float*)d_in[3];
    const float* H2b  = (const float*)d_in[4];
    const float* H3w  = (const float*)d_in[5];
    const float* H3b  = (const float*)d_in[6];
    const float* outw = (const float*)d_in[7];
    const float* outb = (const float*)d_in[8];

    const int B = in_sizes[0] / 256;
    const int blocks = (B + SPB - 1) / SPB;
    const size_t smem = SMEM_FLOATS * sizeof(float);

    prep_kernel<<<24, 256>>>(H1w, H2w, H3w);

    cudaFuncSetAttribute(modernnet_kernel,
                         cudaFuncAttributeMaxDynamicSharedMemorySize, (int)smem);

    modernnet_kernel<<<blocks, NT, smem>>>(x, H1b, H2b, H3b, outw, outb,
                                           (float*)d_out, B);
}